// round 15
// baseline (speedup 1.0000x reference)
#include <cuda_runtime.h>
#include <cuda_fp16.h>
#include <cstdint>
#include <math.h>

// Problem constants
constexpr int B_  = 8;
constexpr int C_  = 256;
constexpr int H_  = 31;
constexpr int W_  = 31;
constexpr int T_  = 7;
constexpr int K_  = 49;      // T*T
constexpr int OC_ = 147;     // 3*K
constexpr int OH_ = 25;
constexpr int OW_ = 25;
constexpr int HW_ = H_ * W_; // 961
constexpr int OHW_= OH_ * OW_; // 625

// GEMM view of the conv: M=5000, N=160(pad), K=2304
// K ordering: k = ((chunk*9 + tap) * 64 + c_local), chunk of 64 channels.
constexpr int NPAD_ = 160;
constexpr int KTOT_ = C_ * 9;        // 2304
constexpr int SB_LD_ = 66;           // padded row length (halves) for s_B
constexpr int SS_LD_ = 66;           // padded channel length for s_sr rows

// Scratch (device globals; no allocations allowed)
__device__ __half g_srH[B_ * HW_ * C_];        // (B,H,W,C) fp16
__device__ __half g_tmplH[B_ * K_ * C_];       // (B,K,C) fp16
__device__ __half g_whk[NPAD_ * KTOT_];        // weights [n][k_reordered] fp16
__device__ float  g_om[B_ * OHW_ * NPAD_];     // conv out [b][pos][n] fp32

__device__ __forceinline__ __half2 u2h(unsigned int u) {
    return *reinterpret_cast<const __half2*>(&u);
}

// ---------------------------------------------------------------------------
// Fused prep: transpose sr (->fp16), transpose tmpl (->fp16),
// weights fp16 reordered to k=(chunk,tap,c64).
// ---------------------------------------------------------------------------
constexpr int PREP_SR_BLKS   = 31 * 8 * 8;                    // 1984
constexpr int PREP_TMPL_BLKS = (B_ * K_ * C_ + 255) / 256;    // 392
constexpr int PREP_W_BLKS    = (NPAD_ * KTOT_ + 255) / 256;   // 1440
constexpr int PREP_BLKS = PREP_SR_BLKS + PREP_TMPL_BLKS + PREP_W_BLKS;

__global__ void __launch_bounds__(256) prep_kernel(
    const float* __restrict__ sr,
    const float* __restrict__ tmpl,
    const float* __restrict__ w)
{
    __shared__ float tile[32][33];
    const int bid = blockIdx.x;
    const int tid = threadIdx.x;

    if (bid < PREP_SR_BLKS) {
        int px = bid % 31;
        int cy = (bid / 31) % 8;
        int b  = bid / (31 * 8);
        int p0 = px * 32, c0 = cy * 32;
        int tx = tid % 32, ty = tid / 32;
        #pragma unroll
        for (int yy = 0; yy < 32; yy += 8) {
            int c = c0 + ty + yy, p = p0 + tx;
            if (p < HW_) tile[ty + yy][tx] = sr[(b * C_ + c) * HW_ + p];
        }
        __syncthreads();
        #pragma unroll
        for (int yy = 0; yy < 32; yy += 8) {
            int p = p0 + ty + yy, c = c0 + tx;
            if (p < HW_) g_srH[(b * HW_ + p) * C_ + c] = __float2half(tile[tx][ty + yy]);
        }
    } else if (bid < PREP_SR_BLKS + PREP_TMPL_BLKS) {
        int t = (bid - PREP_SR_BLKS) * 256 + tid;
        if (t < B_ * K_ * C_) {
            int c = t % C_;
            int k = (t / C_) % K_;
            int b = t / (C_ * K_);
            g_tmplH[t] = __float2half(tmpl[(b * C_ + c) * K_ + k]);
        }
    } else {
        int t = (bid - PREP_SR_BLKS - PREP_TMPL_BLKS) * 256 + tid;
        if (t < NPAD_ * KTOT_) {
            int n    = t / KTOT_;
            int knew = t % KTOT_;
            int ct   = knew / 64;       // chunk*9 + tap
            int cl   = knew % 64;
            int chunk = ct / 9, tap = ct % 9;
            int c = chunk * 64 + cl;
            float v = (n < OC_) ? w[n * KTOT_ + c * 9 + tap] : 0.0f;
            g_whk[t] = __float2half(v);
        }
    }
}

// ---------------------------------------------------------------------------
// K2: conv as implicit GEMM, mma.sync m16n8k16 (fp16 in, fp32 accum).
// grid = (20, 8); block = 256 = 8 warps = 2(M) x 4(N).
// K reordered so each k16 step = 16 consecutive channels at one tap:
// A fragment = single aligned LDS.32 from channel-contiguous s_sr.
// ---------------------------------------------------------------------------
__global__ void __launch_bounds__(256) conv_mma_kernel(
    const float* __restrict__ bias)
{
    __shared__ __half s_B[NPAD_ * SB_LD_];      // 21120 B
    __shared__ __half s_sr[5 * 33 * SS_LD_];    // 21780 B

    const int bm  = blockIdx.x;
    const int b   = blockIdx.y;
    const int tid = threadIdx.x;
    const int wid = tid / 32, lane = tid % 32;
    const int g   = lane / 4;
    const int t2  = (lane % 4) * 2;
    const int warpM = wid % 2;
    const int warpN = wid / 2;

    const int p0     = bm * 32;
    const int i_base = p0 / OW_;

    const int pos0 = p0 + warpM * 16 + g;
    const int pos1 = pos0 + 8;
    const int i0 = pos0 / OW_, j0 = pos0 % OW_;
    const int i1 = pos1 / OW_, j1 = pos1 % OW_;
    const int r0 = i0 - i_base;
    const int r1 = i1 - i_base;

    const __half* srb = g_srH + (size_t)b * HW_ * C_;

    float acc[5][4];
    #pragma unroll
    for (int t = 0; t < 5; t++)
        #pragma unroll
        for (int q = 0; q < 4; q++) acc[t][q] = 0.0f;

    for (int chunk = 0; chunk < 4; chunk++) {
        __syncthreads();
        // stage sr tile: rows i_base-1..i_base+3, cols -1..31, 64 channels
        for (int e = tid; e < 5 * 33 * 32; e += 256) {
            int sp = e / 32, q = e % 32;
            int r = sp / 33, xp = sp % 33;
            int gy = i_base - 1 + r;
            int gx = xp - 1;
            unsigned int val = 0u;
            if (gy >= 0 && gx >= 0 && gx < W_)
                val = *(const unsigned int*)(srb + (size_t)(gy * W_ + gx) * C_ +
                                             chunk * 64 + q * 2);
            *(unsigned int*)(s_sr + sp * SS_LD_ + q * 2) = val;
        }

        for (int tap = 0; tap < 9; tap++) {
            __syncthreads();
            // stage B panel: 160 n x 64 k (this chunk+tap)
            const __half* wsrc = g_whk + (chunk * 9 + tap) * 64;
            for (int e = tid; e < NPAD_ * 32; e += 256) {
                int n = e / 32, q = e % 32;
                *(unsigned int*)(s_B + n * SB_LD_ + q * 2) =
                    *(const unsigned int*)(wsrc + (size_t)n * KTOT_ + q * 2);
            }
            __syncthreads();

            const int dy = tap / 3, dx = tap % 3;
            const __half* a0p = s_sr + ((r0 + dy) * 33 + (j0 + dx)) * SS_LD_;
            const __half* a1p = s_sr + ((r1 + dy) * 33 + (j1 + dx)) * SS_LD_;

            #pragma unroll
            for (int kk = 0; kk < 4; kk++) {
                const int k0 = kk * 16 + t2;
                unsigned int a0 = *(const unsigned int*)(a0p + k0);
                unsigned int a1 = *(const unsigned int*)(a1p + k0);
                unsigned int a2 = *(const unsigned int*)(a0p + k0 + 8);
                unsigned int a3 = *(const unsigned int*)(a1p + k0 + 8);

                #pragma unroll
                for (int t = 0; t < 5; t++) {
                    int n = warpN * 40 + t * 8 + g;
                    const __half* bb = s_B + n * SB_LD_ + k0;
                    unsigned int b0 = *(const unsigned int*)(bb);
                    unsigned int b1 = *(const unsigned int*)(bb + 8);
                    asm volatile(
                        "mma.sync.aligned.m16n8k16.row.col.f32.f16.f16.f32 "
                        "{%0,%1,%2,%3}, {%4,%5,%6,%7}, {%8,%9}, {%0,%1,%2,%3};"
                        : "+f"(acc[t][0]), "+f"(acc[t][1]), "+f"(acc[t][2]), "+f"(acc[t][3])
                        : "r"(a0), "r"(a1), "r"(a2), "r"(a3), "r"(b0), "r"(b1));
                }
            }
        }
    }

    // epilogue: D + bias -> g_om[b][pos][n]
    #pragma unroll
    for (int t = 0; t < 5; t++) {
        int n = warpN * 40 + t * 8 + t2;
        float bv0 = (n     < OC_) ? bias[n]     : 0.0f;
        float bv1 = (n + 1 < OC_) ? bias[n + 1] : 0.0f;
        if (pos0 < OHW_) {
            float2 v = make_float2(acc[t][0] + bv0, acc[t][1] + bv1);
            *(float2*)(g_om + ((size_t)b * OHW_ + pos0) * NPAD_ + n) = v;
        }
        if (pos1 < OHW_) {
            float2 v = make_float2(acc[t][2] + bv0, acc[t][3] + bv1);
            *(float2*)(g_om + ((size_t)b * OHW_ + pos1) * NPAD_ + n) = v;
        }
    }
}

// ---------------------------------------------------------------------------
// K3: deformable bilinear gather + weighted correlation (validated form).
// block = 256 = 8 warps = 8 positions; lane = 8 channels (LDG.128 fp16).
// ---------------------------------------------------------------------------
__global__ void __launch_bounds__(256) deform_xcorr_kernel(float* __restrict__ out)
{
    __shared__ int4  sA4[8][K_];
    __shared__ uint4 sWh[8][K_];

    const int tid = threadIdx.x;

    for (int e = tid; e < 8 * K_; e += 256) {
        const int g2 = e / K_;
        const int k  = e % K_;
        const int p  = blockIdx.x * 8 + g2;
        const int b  = p / OHW_;
        const int rem = p % OHW_;
        const int i  = rem / OW_;
        const int j  = rem % OW_;

        const size_t base = ((size_t)b * OHW_ + rem) * NPAD_;
        float oy = g_om[base + k];
        float ox = g_om[base + k + 49];
        float mz = g_om[base + k + 98];
        float m  = 1.0f / (1.0f + __expf(-mz));

        float ys = (float)i + (float)(k / T_) + oy;
        float xs = (float)j + (float)(k % T_) + ox;
        float y0f = floorf(ys), x0f = floorf(xs);
        float wy = ys - y0f, wx = xs - x0f;
        float y1f = y0f + 1.0f, x1f = x0f + 1.0f;

        bool vy0 = (y0f >= 0.0f) && (y0f <= (float)(H_ - 1));
        bool vy1 = (y1f >= 0.0f) && (y1f <= (float)(H_ - 1));
        bool vx0 = (x0f >= 0.0f) && (x0f <= (float)(W_ - 1));
        bool vx1 = (x1f >= 0.0f) && (x1f <= (float)(W_ - 1));

        float w00 = (1.0f - wy) * (1.0f - wx) * m; if (!(vy0 && vx0)) w00 = 0.0f;
        float w01 = (1.0f - wy) * wx          * m; if (!(vy0 && vx1)) w01 = 0.0f;
        float w10 = wy          * (1.0f - wx) * m; if (!(vy1 && vx0)) w10 = 0.0f;
        float w11 = wy          * wx          * m; if (!(vy1 && vx1)) w11 = 0.0f;

        int y0 = (int)fminf(fmaxf(y0f, 0.0f), (float)(H_ - 1));
        int y1 = (int)fminf(fmaxf(y1f, 0.0f), (float)(H_ - 1));
        int x0 = (int)fminf(fmaxf(x0f, 0.0f), (float)(W_ - 1));
        int x1 = (int)fminf(fmaxf(x1f, 0.0f), (float)(W_ - 1));

        sA4[g2][k] = make_int4((y0 * W_ + x0) * (C_ * 2),
                               (y0 * W_ + x1) * (C_ * 2),
                               (y1 * W_ + x0) * (C_ * 2),
                               (y1 * W_ + x1) * (C_ * 2));
        __half2 h00 = __float2half2_rn(w00);
        __half2 h01 = __float2half2_rn(w01);
        __half2 h10 = __float2half2_rn(w10);
        __half2 h11 = __float2half2_rn(w11);
        sWh[g2][k] = make_uint4(*reinterpret_cast<unsigned int*>(&h00),
                                *reinterpret_cast<unsigned int*>(&h01),
                                *reinterpret_cast<unsigned int*>(&h10),
                                *reinterpret_cast<unsigned int*>(&h11));
    }
    __syncthreads();

    const int g  = tid / 32;
    const int l  = tid % 32;
    const int p  = blockIdx.x * 8 + g;
    const int b  = p / OHW_;
    const int rem = p % OHW_;
    const int i  = rem / OW_;
    const int j  = rem % OW_;

    const char* srHb = (const char*)g_srH + ((size_t)b * HW_ * C_) * 2 + l * 16;
    const char* tHb  = (const char*)g_tmplH + ((size_t)b * K_ * C_) * 2 + l * 16;

    float acc[8];
    #pragma unroll
    for (int q = 0; q < 8; q++) acc[q] = 0.0f;

    #pragma unroll 7
    for (int k = 0; k < K_; k++) {
        int4  a  = sA4[g][k];
        uint4 wh = sWh[g][k];
        __half2 w00 = u2h(wh.x), w01 = u2h(wh.y), w10 = u2h(wh.z), w11 = u2h(wh.w);

        uint4 u00 = *(const uint4*)(srHb + a.x);
        uint4 u01 = *(const uint4*)(srHb + a.y);
        uint4 u10 = *(const uint4*)(srHb + a.z);
        uint4 u11 = *(const uint4*)(srHb + a.w);
        uint4 ut  = *(const uint4*)(tHb + k * (C_ * 2));

        __half2 v0 = __hmul2(w00, u2h(u00.x));
        v0 = __hfma2(w01, u2h(u01.x), v0);
        v0 = __hfma2(w10, u2h(u10.x), v0);
        v0 = __hfma2(w11, u2h(u11.x), v0);
        __half2 v1 = __hmul2(w00, u2h(u00.y));
        v1 = __hfma2(w01, u2h(u01.y), v1);
        v1 = __hfma2(w10, u2h(u10.y), v1);
        v1 = __hfma2(w11, u2h(u11.y), v1);
        __half2 v2 = __hmul2(w00, u2h(u00.z));
        v2 = __hfma2(w01, u2h(u01.z), v2);
        v2 = __hfma2(w10, u2h(u10.z), v2);
        v2 = __hfma2(w11, u2h(u11.z), v2);
        __half2 v3 = __hmul2(w00, u2h(u00.w));
        v3 = __hfma2(w01, u2h(u01.w), v3);
        v3 = __hfma2(w10, u2h(u10.w), v3);
        v3 = __hfma2(w11, u2h(u11.w), v3);

        float2 f0 = __half22float2(v0);
        float2 f1 = __half22float2(v1);
        float2 f2 = __half22float2(v2);
        float2 f3 = __half22float2(v3);
        float2 t0 = __half22float2(u2h(ut.x));
        float2 t1 = __half22float2(u2h(ut.y));
        float2 t2 = __half22float2(u2h(ut.z));
        float2 t3 = __half22float2(u2h(ut.w));

        acc[0] = fmaf(t0.x, f0.x, acc[0]);
        acc[1] = fmaf(t0.y, f0.y, acc[1]);
        acc[2] = fmaf(t1.x, f1.x, acc[2]);
        acc[3] = fmaf(t1.y, f1.y, acc[3]);
        acc[4] = fmaf(t2.x, f2.x, acc[4]);
        acc[5] = fmaf(t2.y, f2.y, acc[5]);
        acc[6] = fmaf(t3.x, f3.x, acc[6]);
        acc[7] = fmaf(t3.y, f3.y, acc[7]);
    }

    const int c = l * 8;
    float* op = out + ((size_t)(b * C_ + c) * OH_ + i) * OW_ + j;
    #pragma unroll
    for (int q = 0; q < 8; q++)
        op[q * OHW_] = acc[q];
}

// ---------------------------------------------------------------------------
extern "C" void kernel_launch(void* const* d_in, const int* in_sizes, int n_in,
                              void* d_out, int out_size)
{
    const float* sr   = (const float*)d_in[0];
    const float* tmpl = (const float*)d_in[1];
    const float* w    = (const float*)d_in[2];
    const float* bias = (const float*)d_in[3];
    float* out = (float*)d_out;

    prep_kernel<<<PREP_BLKS, 256>>>(sr, tmpl, w);
    {
        dim3 g(20, B_);
        conv_mma_kernel<<<g, 256>>>(bias);
    }
    deform_xcorr_kernel<<<625, 256>>>(out);
}

// round 16
// speedup vs baseline: 1.2643x; 1.2643x over previous
#include <cuda_runtime.h>
#include <cuda_fp16.h>
#include <cstdint>
#include <math.h>

// Problem constants
constexpr int B_  = 8;
constexpr int C_  = 256;
constexpr int H_  = 31;
constexpr int W_  = 31;
constexpr int T_  = 7;
constexpr int K_  = 49;      // T*T
constexpr int OC_ = 147;     // 3*K
constexpr int NP_ = 74;      // oc pairs (padded 148)
constexpr int OH_ = 25;
constexpr int OW_ = 25;
constexpr int HW_ = H_ * W_; // 961
constexpr int OHW_= OH_ * OW_; // 625
constexpr int CT_ = 4;       // C split tiles
constexpr int CPT_= C_ / CT_;// 64 channels per tile
constexpr int YT_ = 9;       // y tiles of 3 rows
constexpr int OMLD_ = 160;   // g_om row length (padded oc)

// Scratch (device globals; no allocations allowed)
__device__ __half g_srH[B_ * HW_ * C_];                // (B,H,W,C) fp16
__device__ __half g_tmplH[B_ * K_ * C_];               // (B,K,C) fp16
__device__ float  g_om[B_ * OHW_ * OMLD_];             // conv out [b][pos][oc]
__device__ float  g_part[CT_ * B_ * OC_ * OHW_];       // conv partials
__device__ float2 g_wpk[C_ * NP_ * 9];                 // packed weights [c][pair][tap]

// packed f32x2 helpers
#define FMA_F32X2(d, a, b, c) \
    asm("fma.rn.f32x2 %0, %1, %2, %3;" : "=l"(d) : "l"(a), "l"(b), "l"(c))
#define PACK_DUP(d, v) \
    asm("mov.b64 %0, {%1, %1};" : "=l"(d) : "f"(v))
#define UNPACK2(lo, hi, p) \
    asm("mov.b64 {%0, %1}, %2;" : "=f"(lo), "=f"(hi) : "l"(p))

__device__ __forceinline__ __half2 u2h(unsigned int u) {
    return *reinterpret_cast<const __half2*>(&u);
}

// ---------------------------------------------------------------------------
// Fused prep: transpose sr (->fp16), transpose tmpl (->fp16), pack weights.
// ---------------------------------------------------------------------------
constexpr int PREP_SR_BLKS   = 31 * 8 * 8;                   // 1984
constexpr int PREP_TMPL_BLKS = (B_ * K_ * C_ + 255) / 256;   // 392
constexpr int PREP_PACK_BLKS = (C_ * NP_ * 9 + 255) / 256;   // 666
constexpr int PREP_BLKS = PREP_SR_BLKS + PREP_TMPL_BLKS + PREP_PACK_BLKS;

__global__ void __launch_bounds__(256) prep_kernel(
    const float* __restrict__ sr,
    const float* __restrict__ tmpl,
    const float* __restrict__ w)
{
    __shared__ float tile[32][33];
    const int bid = blockIdx.x;
    const int tid = threadIdx.x;

    if (bid < PREP_SR_BLKS) {
        int px = bid % 31;
        int cy = (bid / 31) % 8;
        int b  = bid / (31 * 8);
        int p0 = px * 32, c0 = cy * 32;
        int tx = tid % 32, ty = tid / 32;
        #pragma unroll
        for (int yy = 0; yy < 32; yy += 8) {
            int c = c0 + ty + yy, p = p0 + tx;
            if (p < HW_) tile[ty + yy][tx] = sr[(b * C_ + c) * HW_ + p];
        }
        __syncthreads();
        #pragma unroll
        for (int yy = 0; yy < 32; yy += 8) {
            int p = p0 + ty + yy, c = c0 + tx;
            if (p < HW_) g_srH[(b * HW_ + p) * C_ + c] = __float2half(tile[tx][ty + yy]);
        }
    } else if (bid < PREP_SR_BLKS + PREP_TMPL_BLKS) {
        int t = (bid - PREP_SR_BLKS) * 256 + tid;
        if (t < B_ * K_ * C_) {
            int c = t % C_;
            int k = (t / C_) % K_;
            int b = t / (C_ * K_);
            g_tmplH[t] = __float2half(tmpl[(b * C_ + c) * K_ + k]);
        }
    } else {
        int t = (bid - PREP_SR_BLKS - PREP_TMPL_BLKS) * 256 + tid;
        if (t < C_ * NP_ * 9) {
            int tap = t % 9;
            int p   = (t / 9) % NP_;
            int c   = t / (9 * NP_);
            int o0 = 2 * p, o1 = 2 * p + 1;
            float v0 = w[o0 * (C_ * 9) + c * 9 + tap];
            float v1 = (o1 < OC_) ? w[o1 * (C_ * 9) + c * 9 + tap] : 0.0f;
            g_wpk[t] = make_float2(v0, v1);
        }
    }
}

// ---------------------------------------------------------------------------
// K2: 3x3 conv (validated R13 form). grid=(9,8,4)=288 blocks, 1 wave.
// block=384; og=tid/5 (74 oc-pairs), xg=tid%5, 3 output rows.
// ---------------------------------------------------------------------------
__global__ void __launch_bounds__(384, 2) conv_om_kernel(
    const float* __restrict__ sr)
{
    __shared__ float s_sr[CPT_][5][33];   // 42.2 KB

    const int by = blockIdx.x;
    const int b  = blockIdx.y;
    const int ct = blockIdx.z;
    const int tid = threadIdx.x;

    const int og = tid / 5;
    const int xg = tid % 5;
    const bool active = (og < NP_);
    const int x_base = xg * 5;
    const int y_base = by * 3;
    const int cbase  = ct * CPT_;

    for (int e = tid; e < CPT_ * 5 * 33; e += 384) {
        int cc  = e / 165;
        int rem = e % 165;
        int r   = rem / 33;
        int xp  = rem % 33;
        int gy  = y_base + r - 1;
        int gx  = xp - 1;
        float v = 0.f;
        if (gy >= 0 && gy < H_ && gx >= 0 && gx < W_)
            v = sr[((b * C_ + cbase + cc) * H_ + gy) * W_ + gx];
        s_sr[cc][r][xp] = v;
    }
    __syncthreads();

    unsigned long long acc[3][5];
    #pragma unroll
    for (int yy = 0; yy < 3; yy++)
        #pragma unroll
        for (int xx = 0; xx < 5; xx++) acc[yy][xx] = 0ull;

    if (active) {
        const unsigned long long* __restrict__ wp0 =
            (const unsigned long long*)g_wpk + (size_t)og * 9;
        #pragma unroll 2
        for (int c = 0; c < CPT_; c++) {
            unsigned long long wq[9];
            const unsigned long long* wp = wp0 + (size_t)(cbase + c) * (NP_ * 9);
            #pragma unroll
            for (int t = 0; t < 9; t++) wq[t] = __ldg(wp + t);

            #pragma unroll
            for (int ir = 0; ir < 5; ir++) {
                #pragma unroll
                for (int u = 0; u < 7; u++) {
                    unsigned long long rp;
                    {
                        float v = s_sr[c][ir][x_base + u];
                        PACK_DUP(rp, v);
                    }
                    #pragma unroll
                    for (int dx = 0; dx < 3; dx++) {
                        const int xx = u - dx;
                        if (xx >= 0 && xx < 5) {
                            #pragma unroll
                            for (int dy = 0; dy < 3; dy++) {
                                const int yy = ir - dy;
                                if (yy >= 0 && yy < 3)
                                    FMA_F32X2(acc[yy][xx], rp,
                                              wq[dy * 3 + dx], acc[yy][xx]);
                            }
                        }
                    }
                }
            }
        }

        int o_even = og * 2;
        #pragma unroll
        for (int yy = 0; yy < 3; yy++) {
            int y = y_base + yy;
            if (y >= OH_) continue;
            #pragma unroll
            for (int xx = 0; xx < 5; xx++) {
                float lo, hi;
                UNPACK2(lo, hi, acc[yy][xx]);
                int base = ct * (B_ * OC_ * OHW_) +
                           (b * OC_ + o_even) * OHW_ + y * OW_ + x_base + xx;
                g_part[base] = lo;
                if (o_even + 1 < OC_) g_part[base + OHW_] = hi;
            }
        }
    }
}

// ---------------------------------------------------------------------------
// Reduce + transpose: sum CT_ partials + bias, write g_om[b][pos][oc] (padded
// row 160). grid = (20, 8) blocks of 256; 32 positions per block.
// Reads coalesced over pos; writes coalesced over oc via smem tile.
// ---------------------------------------------------------------------------
__global__ void __launch_bounds__(256) reduce_om_kernel(const float* __restrict__ bias) {
    __shared__ float s[32][161];   // padded: stride 161 avoids bank conflicts

    const int b  = blockIdx.y;
    const int p0 = blockIdx.x * 32;
    const int tid = threadIdx.x;

    for (int e = tid; e < OC_ * 32; e += 256) {
        int oc = e / 32;
        int pp = e % 32;
        int pos = p0 + pp;
        if (pos < OHW_) {
            float v = bias[oc];
            int idx = (b * OC_ + oc) * OHW_ + pos;
            #pragma unroll
            for (int ct = 0; ct < CT_; ct++)
                v += g_part[ct * (B_ * OC_ * OHW_) + idx];
            s[pp][oc] = v;
        }
    }
    __syncthreads();

    for (int e = tid; e < 32 * OMLD_; e += 256) {
        int pp = e / OMLD_;
        int oc = e % OMLD_;
        int pos = p0 + pp;
        if (pos < OHW_ && oc < OC_)
            g_om[((size_t)b * OHW_ + pos) * OMLD_ + oc] = s[pp][oc];
    }
}

// ---------------------------------------------------------------------------
// K3: deformable bilinear gather + weighted correlation (validated R13 form;
// metadata reads now coalesced from g_om[b][pos][oc]).
// block = 256 = 8 warps = 8 positions; lane = 8 channels (LDG.128 fp16).
// ---------------------------------------------------------------------------
__global__ void __launch_bounds__(256) deform_xcorr_kernel(float* __restrict__ out)
{
    __shared__ int4  sA4[8][K_];
    __shared__ uint4 sWh[8][K_];

    const int tid = threadIdx.x;

    for (int e = tid; e < 8 * K_; e += 256) {
        const int g2 = e / K_;
        const int k  = e % K_;
        const int p  = blockIdx.x * 8 + g2;
        const int b  = p / OHW_;
        const int rem = p % OHW_;
        const int i  = rem / OW_;
        const int j  = rem % OW_;

        const size_t base = ((size_t)b * OHW_ + rem) * OMLD_;
        float oy = g_om[base + k];
        float ox = g_om[base + k + 49];
        float mz = g_om[base + k + 98];
        float m  = 1.0f / (1.0f + __expf(-mz));

        float ys = (float)i + (float)(k / T_) + oy;
        float xs = (float)j + (float)(k % T_) + ox;
        float y0f = floorf(ys), x0f = floorf(xs);
        float wy = ys - y0f, wx = xs - x0f;
        float y1f = y0f + 1.0f, x1f = x0f + 1.0f;

        bool vy0 = (y0f >= 0.0f) && (y0f <= (float)(H_ - 1));
        bool vy1 = (y1f >= 0.0f) && (y1f <= (float)(H_ - 1));
        bool vx0 = (x0f >= 0.0f) && (x0f <= (float)(W_ - 1));
        bool vx1 = (x1f >= 0.0f) && (x1f <= (float)(W_ - 1));

        float w00 = (1.0f - wy) * (1.0f - wx) * m; if (!(vy0 && vx0)) w00 = 0.0f;
        float w01 = (1.0f - wy) * wx          * m; if (!(vy0 && vx1)) w01 = 0.0f;
        float w10 = wy          * (1.0f - wx) * m; if (!(vy1 && vx0)) w10 = 0.0f;
        float w11 = wy          * wx          * m; if (!(vy1 && vx1)) w11 = 0.0f;

        int y0 = (int)fminf(fmaxf(y0f, 0.0f), (float)(H_ - 1));
        int y1 = (int)fminf(fmaxf(y1f, 0.0f), (float)(H_ - 1));
        int x0 = (int)fminf(fmaxf(x0f, 0.0f), (float)(W_ - 1));
        int x1 = (int)fminf(fmaxf(x1f, 0.0f), (float)(W_ - 1));

        sA4[g2][k] = make_int4((y0 * W_ + x0) * (C_ * 2),
                               (y0 * W_ + x1) * (C_ * 2),
                               (y1 * W_ + x0) * (C_ * 2),
                               (y1 * W_ + x1) * (C_ * 2));
        __half2 h00 = __float2half2_rn(w00);
        __half2 h01 = __float2half2_rn(w01);
        __half2 h10 = __float2half2_rn(w10);
        __half2 h11 = __float2half2_rn(w11);
        sWh[g2][k] = make_uint4(*reinterpret_cast<unsigned int*>(&h00),
                                *reinterpret_cast<unsigned int*>(&h01),
                                *reinterpret_cast<unsigned int*>(&h10),
                                *reinterpret_cast<unsigned int*>(&h11));
    }
    __syncthreads();

    const int g  = tid / 32;
    const int l  = tid % 32;
    const int p  = blockIdx.x * 8 + g;
    const int b  = p / OHW_;
    const int rem = p % OHW_;
    const int i  = rem / OW_;
    const int j  = rem % OW_;

    const char* srHb = (const char*)g_srH + ((size_t)b * HW_ * C_) * 2 + l * 16;
    const char* tHb  = (const char*)g_tmplH + ((size_t)b * K_ * C_) * 2 + l * 16;

    float acc[8];
    #pragma unroll
    for (int q = 0; q < 8; q++) acc[q] = 0.0f;

    #pragma unroll 7
    for (int k = 0; k < K_; k++) {
        int4  a  = sA4[g][k];
        uint4 wh = sWh[g][k];
        __half2 w00 = u2h(wh.x), w01 = u2h(wh.y), w10 = u2h(wh.z), w11 = u2h(wh.w);

        uint4 u00 = *(const uint4*)(srHb + a.x);
        uint4 u01 = *(const uint4*)(srHb + a.y);
        uint4 u10 = *(const uint4*)(srHb + a.z);
        uint4 u11 = *(const uint4*)(srHb + a.w);
        uint4 ut  = *(const uint4*)(tHb + k * (C_ * 2));

        __half2 v0 = __hmul2(w00, u2h(u00.x));
        v0 = __hfma2(w01, u2h(u01.x), v0);
        v0 = __hfma2(w10, u2h(u10.x), v0);
        v0 = __hfma2(w11, u2h(u11.x), v0);
        __half2 v1 = __hmul2(w00, u2h(u00.y));
        v1 = __hfma2(w01, u2h(u01.y), v1);
        v1 = __hfma2(w10, u2h(u10.y), v1);
        v1 = __hfma2(w11, u2h(u11.y), v1);
        __half2 v2 = __hmul2(w00, u2h(u00.z));
        v2 = __hfma2(w01, u2h(u01.z), v2);
        v2 = __hfma2(w10, u2h(u10.z), v2);
        v2 = __hfma2(w11, u2h(u11.z), v2);
        __half2 v3 = __hmul2(w00, u2h(u00.w));
        v3 = __hfma2(w01, u2h(u01.w), v3);
        v3 = __hfma2(w10, u2h(u10.w), v3);
        v3 = __hfma2(w11, u2h(u11.w), v3);

        float2 f0 = __half22float2(v0);
        float2 f1 = __half22float2(v1);
        float2 f2 = __half22float2(v2);
        float2 f3 = __half22float2(v3);
        float2 t0 = __half22float2(u2h(ut.x));
        float2 t1 = __half22float2(u2h(ut.y));
        float2 t2 = __half22float2(u2h(ut.z));
        float2 t3 = __half22float2(u2h(ut.w));

        acc[0] = fmaf(t0.x, f0.x, acc[0]);
        acc[1] = fmaf(t0.y, f0.y, acc[1]);
        acc[2] = fmaf(t1.x, f1.x, acc[2]);
        acc[3] = fmaf(t1.y, f1.y, acc[3]);
        acc[4] = fmaf(t2.x, f2.x, acc[4]);
        acc[5] = fmaf(t2.y, f2.y, acc[5]);
        acc[6] = fmaf(t3.x, f3.x, acc[6]);
        acc[7] = fmaf(t3.y, f3.y, acc[7]);
    }

    const int c = l * 8;
    float* op = out + ((size_t)(b * C_ + c) * OH_ + i) * OW_ + j;
    #pragma unroll
    for (int q = 0; q < 8; q++)
        op[q * OHW_] = acc[q];
}

// ---------------------------------------------------------------------------
extern "C" void kernel_launch(void* const* d_in, const int* in_sizes, int n_in,
                              void* d_out, int out_size)
{
    const float* sr   = (const float*)d_in[0];
    const float* tmpl = (const float*)d_in[1];
    const float* w    = (const float*)d_in[2];
    const float* bias = (const float*)d_in[3];
    float* out = (float*)d_out;

    prep_kernel<<<PREP_BLKS, 256>>>(sr, tmpl, w);
    {
        dim3 g(YT_, B_, CT_);
        conv_om_kernel<<<g, 384>>>(sr);
    }
    {
        dim3 g((OHW_ + 31) / 32, B_);
        reduce_om_kernel<<<g, 256>>>(bias);
    }
    deform_xcorr_kernel<<<625, 256>>>(out);
}